// round 1
// baseline (speedup 1.0000x reference)
#include <cuda_runtime.h>

#define BB 2
#define NN 4096           // H*W
#define CC 256            // QK_DIM == IMG_DIM == VOXEL_DIM
#define CV 512            // concat V width (img 256 + pc 256)

// ---- scratch (device globals; allocation-free per harness rules) ----
__device__ float g_pc2[(size_t)BB * CC * NN];        // [B][256][N]   8 MB
__device__ float g_Q  [(size_t)BB * NN * CC];        // [B][N][256]   8 MB
__device__ float g_K  [(size_t)BB * NN * CC];        // [B][N][256]   8 MB
__device__ float g_V  [(size_t)BB * NN * CV];        // [B][N][512]  16 MB
__device__ float g_S  [(size_t)BB * NN * NN];        // [B][N][N]   128 MB

// ---------------------------------------------------------------------------
// 1) repack pc [B,D=16,H,W,C=16] -> pc2 [B, c*16+d, h*64+w]
// ---------------------------------------------------------------------------
__global__ __launch_bounds__(256) void repack_pc_kernel(const float* __restrict__ pc)
{
    __shared__ float sm[16][65];
    int bdh = blockIdx.x;              // b*1024 + d*64 + h
    int h = bdh & 63;
    int d = (bdh >> 6) & 15;
    int b = bdh >> 10;
    const float* src = pc + (size_t)bdh * 1024;   // (w, c) contiguous block
    int t = threadIdx.x;
    #pragma unroll
    for (int i = t; i < 1024; i += 256) {
        int w = i >> 4, c = i & 15;
        sm[c][w] = src[i];
    }
    __syncthreads();
    #pragma unroll
    for (int i = t; i < 1024; i += 256) {
        int c = i >> 6, w = i & 63;
        g_pc2[((size_t)(b * CC + c * 16 + d)) * NN + h * 64 + w] = sm[c][w];
    }
}

// ---------------------------------------------------------------------------
// 2) projections: C[b][n][o] = sum_c A[b][c][n] * W[o][c] + bias[o]
//    job 0: Q = img_conv(img)      -> g_Q
//    job 1: K = voxel_conv(pc2)    -> g_K
//    job 2: Vimg = img_v(img)      -> g_V cols [0,256)
//    job 3: Vpc  = voxel_v(pc2)    -> g_V cols [256,512)
//    128(n) x 128(o) x 8 tiles, 256 threads, 8x8 per thread
// ---------------------------------------------------------------------------
__global__ __launch_bounds__(256) void proj_kernel(
    const float* __restrict__ img,
    const float* __restrict__ wq,  const float* __restrict__ bq,
    const float* __restrict__ wk,  const float* __restrict__ bk,
    const float* __restrict__ wvi, const float* __restrict__ bvi,
    const float* __restrict__ wvp, const float* __restrict__ bvp)
{
    int zb  = blockIdx.z;
    int job = zb & 3;
    int b   = zb >> 2;

    const float* A;  const float* W;  const float* bias;
    float* C;  int ldC;  int coff;
    switch (job) {
        case 0:  A = img   + (size_t)b * CC * NN; W = wq;  bias = bq;
                 C = g_Q   + (size_t)b * NN * CC; ldC = CC; coff = 0;   break;
        case 1:  A = g_pc2 + (size_t)b * CC * NN; W = wk;  bias = bk;
                 C = g_K   + (size_t)b * NN * CC; ldC = CC; coff = 0;   break;
        case 2:  A = img   + (size_t)b * CC * NN; W = wvi; bias = bvi;
                 C = g_V   + (size_t)b * NN * CV; ldC = CV; coff = 0;   break;
        default: A = g_pc2 + (size_t)b * CC * NN; W = wvp; bias = bvp;
                 C = g_V   + (size_t)b * NN * CV; ldC = CV; coff = 256; break;
    }

    int n0 = blockIdx.x * 128;
    int o0 = blockIdx.y * 128;

    __shared__ float As[8][128];   // [k][n]
    __shared__ float Bs[8][128];   // [k][o]

    int t  = threadIdx.x;
    int tx = t & 15, ty = t >> 4;

    int ak  = t >> 5;            // 0..7
    int an  = (t & 31) * 4;      // 0..124
    int wo  = t >> 1;            // 0..127
    int wk4 = (t & 1) * 4;       // 0 or 4

    float acc[8][8] = {};

    for (int k0 = 0; k0 < CC; k0 += 8) {
        float4 av = *(const float4*)(A + (size_t)(k0 + ak) * NN + n0 + an);
        *(float4*)&As[ak][an] = av;
        float4 wv = *(const float4*)(W + (size_t)(o0 + wo) * CC + k0 + wk4);
        Bs[wk4 + 0][wo] = wv.x;
        Bs[wk4 + 1][wo] = wv.y;
        Bs[wk4 + 2][wo] = wv.z;
        Bs[wk4 + 3][wo] = wv.w;
        __syncthreads();
        #pragma unroll
        for (int k = 0; k < 8; k++) {
            float ar[8], br[8];
            *(float4*)&ar[0] = *(float4*)&As[k][ty * 4];
            *(float4*)&ar[4] = *(float4*)&As[k][ty * 4 + 64];
            *(float4*)&br[0] = *(float4*)&Bs[k][tx * 4];
            *(float4*)&br[4] = *(float4*)&Bs[k][tx * 4 + 64];
            #pragma unroll
            for (int i = 0; i < 8; i++)
                #pragma unroll
                for (int j = 0; j < 8; j++)
                    acc[i][j] += ar[i] * br[j];
        }
        __syncthreads();
    }

    #pragma unroll
    for (int i = 0; i < 8; i++) {
        int n = n0 + ((i < 4) ? (ty * 4 + i) : (64 + ty * 4 + (i - 4)));
        #pragma unroll
        for (int jh = 0; jh < 2; jh++) {
            int ol = o0 + ((jh == 0) ? (tx * 4) : (64 + tx * 4));   // local W row
            float4 v;
            v.x = acc[i][jh * 4 + 0] + bias[ol + 0];
            v.y = acc[i][jh * 4 + 1] + bias[ol + 1];
            v.z = acc[i][jh * 4 + 2] + bias[ol + 2];
            v.w = acc[i][jh * 4 + 3] + bias[ol + 3];
            *(float4*)(C + (size_t)n * ldC + coff + ol) = v;
        }
    }
}

// ---------------------------------------------------------------------------
// 3) S[b][m][n] = sum_k Q[b][m][k] * K[b][n][k]
// ---------------------------------------------------------------------------
__global__ __launch_bounds__(256) void qk_kernel()
{
    int b  = blockIdx.z;
    int m0 = blockIdx.y * 128;
    int n0 = blockIdx.x * 128;
    const float* Q = g_Q + (size_t)b * NN * CC;
    const float* K = g_K + (size_t)b * NN * CC;
    float*       S = g_S + (size_t)b * NN * NN;

    __shared__ float As[8][128];   // [k][m]
    __shared__ float Bs[8][128];   // [k][n]

    int t  = threadIdx.x;
    int tx = t & 15, ty = t >> 4;
    int r  = t >> 1;               // 0..127
    int kq = (t & 1) * 4;          // 0 or 4

    float acc[8][8] = {};

    for (int k0 = 0; k0 < CC; k0 += 8) {
        float4 qv = *(const float4*)(Q + (size_t)(m0 + r) * CC + k0 + kq);
        As[kq + 0][r] = qv.x; As[kq + 1][r] = qv.y;
        As[kq + 2][r] = qv.z; As[kq + 3][r] = qv.w;
        float4 kv = *(const float4*)(K + (size_t)(n0 + r) * CC + k0 + kq);
        Bs[kq + 0][r] = kv.x; Bs[kq + 1][r] = kv.y;
        Bs[kq + 2][r] = kv.z; Bs[kq + 3][r] = kv.w;
        __syncthreads();
        #pragma unroll
        for (int k = 0; k < 8; k++) {
            float ar[8], br[8];
            *(float4*)&ar[0] = *(float4*)&As[k][ty * 4];
            *(float4*)&ar[4] = *(float4*)&As[k][ty * 4 + 64];
            *(float4*)&br[0] = *(float4*)&Bs[k][tx * 4];
            *(float4*)&br[4] = *(float4*)&Bs[k][tx * 4 + 64];
            #pragma unroll
            for (int i = 0; i < 8; i++)
                #pragma unroll
                for (int j = 0; j < 8; j++)
                    acc[i][j] += ar[i] * br[j];
        }
        __syncthreads();
    }

    #pragma unroll
    for (int i = 0; i < 8; i++) {
        int m = m0 + ((i < 4) ? (ty * 4 + i) : (64 + ty * 4 + (i - 4)));
        #pragma unroll
        for (int jh = 0; jh < 2; jh++) {
            int n = n0 + ((jh == 0) ? (tx * 4) : (64 + tx * 4));
            float4 v;
            v.x = acc[i][jh * 4 + 0];
            v.y = acc[i][jh * 4 + 1];
            v.z = acc[i][jh * 4 + 2];
            v.w = acc[i][jh * 4 + 3];
            *(float4*)(S + (size_t)m * NN + n) = v;
        }
    }
}

// ---------------------------------------------------------------------------
// 4) row softmax over g_S rows (length 4096), in place
// ---------------------------------------------------------------------------
__global__ __launch_bounds__(256) void softmax_kernel()
{
    size_t row = blockIdx.x;
    float* p = g_S + row * NN;
    int t = threadIdx.x;

    float4 v[4];
    #pragma unroll
    for (int i = 0; i < 4; i++) v[i] = ((const float4*)p)[(size_t)i * 256 + t];

    float mx = -1e30f;
    #pragma unroll
    for (int i = 0; i < 4; i++) {
        mx = fmaxf(mx, fmaxf(fmaxf(v[i].x, v[i].y), fmaxf(v[i].z, v[i].w)));
    }
    __shared__ float red[8];
    #pragma unroll
    for (int o = 16; o; o >>= 1) mx = fmaxf(mx, __shfl_xor_sync(0xFFFFFFFFu, mx, o));
    if ((t & 31) == 0) red[t >> 5] = mx;
    __syncthreads();
    if (t < 8) {
        float m = red[t];
        #pragma unroll
        for (int o = 4; o; o >>= 1) m = fmaxf(m, __shfl_xor_sync(0xFFu, m, o));
        if (t == 0) red[0] = m;
    }
    __syncthreads();
    mx = red[0];
    __syncthreads();

    float s = 0.f;
    #pragma unroll
    for (int i = 0; i < 4; i++) {
        v[i].x = __expf(v[i].x - mx); s += v[i].x;
        v[i].y = __expf(v[i].y - mx); s += v[i].y;
        v[i].z = __expf(v[i].z - mx); s += v[i].z;
        v[i].w = __expf(v[i].w - mx); s += v[i].w;
    }
    #pragma unroll
    for (int o = 16; o; o >>= 1) s += __shfl_xor_sync(0xFFFFFFFFu, s, o);
    if ((t & 31) == 0) red[t >> 5] = s;
    __syncthreads();
    if (t < 8) {
        float m = red[t];
        #pragma unroll
        for (int o = 4; o; o >>= 1) m += __shfl_xor_sync(0xFFu, m, o);
        if (t == 0) red[0] = m;
    }
    __syncthreads();
    float inv = 1.0f / red[0];

    #pragma unroll
    for (int i = 0; i < 4; i++) {
        v[i].x *= inv; v[i].y *= inv; v[i].z *= inv; v[i].w *= inv;
        ((float4*)p)[(size_t)i * 256 + t] = v[i];
    }
}

// ---------------------------------------------------------------------------
// 5) O[b][m][c] = sum_n P[b][m][n] * V[b][n][c], c in [0,512)
//    epilogue writes transposed directly into d_out:
//      c < 256  -> img_v  at out[(b*256+c)*N + m]
//      c >= 256 -> pc_v   at out[B*256*N + (b*256+(c-256))*N + m]
// ---------------------------------------------------------------------------
__global__ __launch_bounds__(256) void out_kernel(float* __restrict__ out)
{
    int b  = blockIdx.z;
    int m0 = blockIdx.x * 128;     // 32 tiles
    int c0 = blockIdx.y * 128;     // 4 tiles
    const float* P = g_S + (size_t)b * NN * NN;
    const float* V = g_V + (size_t)b * NN * CV;

    __shared__ float As[8][128];   // [k][m]
    __shared__ float Bs[8][128];   // [k][c]

    int t  = threadIdx.x;
    int tx = t & 15, ty = t >> 4;
    int r  = t >> 1;               // 0..127
    int kq = (t & 1) * 4;
    int vk = t >> 5;               // 0..7
    int vc = (t & 31) * 4;

    float acc[8][8] = {};

    for (int k0 = 0; k0 < NN; k0 += 8) {
        float4 pv = *(const float4*)(P + (size_t)(m0 + r) * NN + k0 + kq);
        As[kq + 0][r] = pv.x; As[kq + 1][r] = pv.y;
        As[kq + 2][r] = pv.z; As[kq + 3][r] = pv.w;
        float4 vv = *(const float4*)(V + (size_t)(k0 + vk) * CV + c0 + vc);
        *(float4*)&Bs[vk][vc] = vv;
        __syncthreads();
        #pragma unroll
        for (int k = 0; k < 8; k++) {
            float ar[8], br[8];
            *(float4*)&ar[0] = *(float4*)&As[k][ty * 4];
            *(float4*)&ar[4] = *(float4*)&As[k][ty * 4 + 64];
            *(float4*)&br[0] = *(float4*)&Bs[k][tx * 4];
            *(float4*)&br[4] = *(float4*)&Bs[k][tx * 4 + 64];
            #pragma unroll
            for (int i = 0; i < 8; i++)
                #pragma unroll
                for (int j = 0; j < 8; j++)
                    acc[i][j] += ar[i] * br[j];
        }
        __syncthreads();
    }

    const size_t pcOff = (size_t)BB * 256 * NN;
    #pragma unroll
    for (int jh = 0; jh < 2; jh++) {
        #pragma unroll
        for (int j = 0; j < 4; j++) {
            int c = c0 + ((jh == 0) ? (tx * 4 + j) : (64 + tx * 4 + j));
            float* base;
            if (c < 256) base = out + (size_t)(b * 256 + c) * NN;
            else         base = out + pcOff + (size_t)(b * 256 + (c - 256)) * NN;
            float4 v0 = make_float4(acc[0][jh * 4 + j], acc[1][jh * 4 + j],
                                    acc[2][jh * 4 + j], acc[3][jh * 4 + j]);
            *(float4*)(base + m0 + ty * 4) = v0;
            float4 v1 = make_float4(acc[4][jh * 4 + j], acc[5][jh * 4 + j],
                                    acc[6][jh * 4 + j], acc[7][jh * 4 + j]);
            *(float4*)(base + m0 + 64 + ty * 4) = v1;
        }
    }
}

// ---------------------------------------------------------------------------
extern "C" void kernel_launch(void* const* d_in, const int* in_sizes, int n_in,
                              void* d_out, int out_size)
{
    const float* img  = (const float*)d_in[0];
    const float* pc   = (const float*)d_in[1];
    const float* w_q  = (const float*)d_in[2];
    const float* b_q  = (const float*)d_in[3];
    const float* w_k  = (const float*)d_in[4];
    const float* b_k  = (const float*)d_in[5];
    const float* w_vi = (const float*)d_in[6];
    const float* b_vi = (const float*)d_in[7];
    const float* w_vp = (const float*)d_in[8];
    const float* b_vp = (const float*)d_in[9];
    float* out = (float*)d_out;

    repack_pc_kernel<<<BB * 16 * 64, 256>>>(pc);
    proj_kernel<<<dim3(NN / 128, CC / 128, BB * 4), 256>>>(
        img, w_q, b_q, w_k, b_k, w_vi, b_vi, w_vp, b_vp);
    qk_kernel<<<dim3(NN / 128, NN / 128, BB), 256>>>();
    softmax_kernel<<<BB * NN, 256>>>();
    out_kernel<<<dim3(NN / 128, CV / 128, BB), 256>>>(out);
}

// round 4
// speedup vs baseline: 2.2488x; 2.2488x over previous
#include <cuda_runtime.h>
#include <cstdint>

#define BB 2
#define NN 4096           // H*W
#define CC 256            // QK_DIM
#define CV 512            // concat V width

// ---- scratch (device globals; allocation-free) ----
__device__ float g_imgT[(size_t)BB * NN * CC];   // [b][n][256]
__device__ float g_pcT [(size_t)BB * NN * CC];   // [b][n][256]  col = c*16+d
__device__ float g_Q   [(size_t)BB * NN * CC];   // [b][n][256]
__device__ float g_K   [(size_t)BB * NN * CC];   // [b][n][256]
__device__ float g_Vt  [(size_t)BB * CV * NN];   // [b][c(512)][n]
__device__ float g_S   [(size_t)BB * NN * NN];   // [b][m][n]

// ===========================================================================
// helpers
// ===========================================================================
__device__ __forceinline__ uint32_t f2u(float x) { return __float_as_uint(x); }
__device__ __forceinline__ uint32_t tf32rn_u(float x) {
    uint32_t r; asm("cvt.rna.tf32.f32 %0, %1;" : "=r"(r) : "f"(x)); return r;
}
__device__ __forceinline__ float hi10(float x) {
    return __uint_as_float(f2u(x) & 0xFFFFE000u);   // exact in tf32 (10 mant bits)
}

__device__ __forceinline__ void mma8(float* d, const uint32_t* a, const uint32_t* b) {
    asm("mma.sync.aligned.m16n8k8.row.col.f32.tf32.tf32.f32 "
        "{%0,%1,%2,%3}, {%4,%5,%6,%7}, {%8,%9}, {%0,%1,%2,%3};"
        : "+f"(d[0]), "+f"(d[1]), "+f"(d[2]), "+f"(d[3])
        : "r"(a[0]), "r"(a[1]), "r"(a[2]), "r"(a[3]), "r"(b[0]), "r"(b[1]));
}

// ===========================================================================
// tf32 mma.sync GEMM core.
//   C[128][BN] += A[aRow0..+128][K] * B[bRow0..+BN][K]^T
//   A, B row-major K-major. Threads = BN (4 or 8 warps), warp tile 64x64.
//   smem tile rows padded to RS = CH+4 floats (conflict-free LDS.32 / STS.128).
//   SPLIT: hi/lo 2-term tf32 split of BOTH operands, 3 MMAs per product.
// ===========================================================================
template<int BN, int CH, bool SPLIT>
struct GemmCfg {
    static constexpr int T    = BN;
    static constexpr int RS   = CH + 4;
    static constexpr int AF   = 128 * RS;      // A tile floats (one copy)
    static constexpr int BFl  = BN * RS;
    static constexpr int TILE = SPLIT ? 2 * (AF + BFl) : (AF + BFl);   // floats/stage
    static constexpr int NA   = (128 * CH / 4) / T;   // float4 per thread (A)
    static constexpr int NB   = (BN * CH / 4) / T;
    static constexpr int CHJ  = CH / 4;
    static constexpr int SMEM_BYTES =
        (2 * TILE * 4 > 132 * 128 * 4) ? 2 * TILE * 4 : 132 * 128 * 4;
};

template<int BN, int CH, bool SPLIT>
__device__ __forceinline__ void gemm_run(
    const float* __restrict__ A, int lda, int aRow0,
    const float* __restrict__ B, int ldb, int bRow0,
    int K, float* sm, float (&acc)[4][8][4])
{
    using G = GemmCfg<BN, CH, SPLIT>;
    const int t    = threadIdx.x;
    const int lane = t & 31;
    const int wid  = t >> 5;
    const int wm   = wid & 1;
    const int wn   = wid >> 1;
    const int KC   = K / CH;

    float4 ra[G::NA], rb[G::NB];

    // ---- stage loaders -----------------------------------------------------
    auto LD = [&](int c) {
        const int k0 = c * CH;
        #pragma unroll
        for (int i = 0; i < G::NA; i++) {
            int f = t + i * G::T, m = f / G::CHJ, j = f % G::CHJ;
            ra[i] = *(const float4*)(A + (size_t)(aRow0 + m) * lda + k0 + 4 * j);
        }
        #pragma unroll
        for (int i = 0; i < G::NB; i++) {
            int f = t + i * G::T, m = f / G::CHJ, j = f % G::CHJ;
            rb[i] = *(const float4*)(B + (size_t)(bRow0 + m) * ldb + k0 + 4 * j);
        }
    };
    auto ST = [&](int buf) {
        float* S = sm + buf * G::TILE;
        if (!SPLIT) {
            #pragma unroll
            for (int i = 0; i < G::NA; i++) {
                int f = t + i * G::T, m = f / G::CHJ, j = f % G::CHJ;
                float4 v = ra[i], o;
                o.x = __uint_as_float(tf32rn_u(v.x));
                o.y = __uint_as_float(tf32rn_u(v.y));
                o.z = __uint_as_float(tf32rn_u(v.z));
                o.w = __uint_as_float(tf32rn_u(v.w));
                *(float4*)(S + m * G::RS + 4 * j) = o;
            }
            #pragma unroll
            for (int i = 0; i < G::NB; i++) {
                int f = t + i * G::T, m = f / G::CHJ, j = f % G::CHJ;
                float4 v = rb[i], o;
                o.x = __uint_as_float(tf32rn_u(v.x));
                o.y = __uint_as_float(tf32rn_u(v.y));
                o.z = __uint_as_float(tf32rn_u(v.z));
                o.w = __uint_as_float(tf32rn_u(v.w));
                *(float4*)(S + G::AF + m * G::RS + 4 * j) = o;
            }
        } else {
            float* SAh = S;
            float* SAl = S + G::AF;
            float* SBh = S + 2 * G::AF;
            float* SBl = SBh + G::BFl;
            #pragma unroll
            for (int i = 0; i < G::NA; i++) {
                int f = t + i * G::T, m = f / G::CHJ, j = f % G::CHJ;
                float4 v = ra[i], h, l;
                h.x = hi10(v.x); l.x = __uint_as_float(tf32rn_u(v.x - h.x));
                h.y = hi10(v.y); l.y = __uint_as_float(tf32rn_u(v.y - h.y));
                h.z = hi10(v.z); l.z = __uint_as_float(tf32rn_u(v.z - h.z));
                h.w = hi10(v.w); l.w = __uint_as_float(tf32rn_u(v.w - h.w));
                int off = m * G::RS + 4 * j;
                *(float4*)(SAh + off) = h;
                *(float4*)(SAl + off) = l;
            }
            #pragma unroll
            for (int i = 0; i < G::NB; i++) {
                int f = t + i * G::T, m = f / G::CHJ, j = f % G::CHJ;
                float4 v = rb[i], h, l;
                h.x = hi10(v.x); l.x = __uint_as_float(tf32rn_u(v.x - h.x));
                h.y = hi10(v.y); l.y = __uint_as_float(tf32rn_u(v.y - h.y));
                h.z = hi10(v.z); l.z = __uint_as_float(tf32rn_u(v.z - h.z));
                h.w = hi10(v.w); l.w = __uint_as_float(tf32rn_u(v.w - h.w));
                int off = m * G::RS + 4 * j;
                *(float4*)(SBh + off) = h;
                *(float4*)(SBl + off) = l;
            }
        }
    };
    // ---- compute -----------------------------------------------------------
    auto CMP = [&](int buf) {
        const uint32_t* S  = (const uint32_t*)(sm + buf * G::TILE);
        const uint32_t* SA = S;
        const uint32_t* SB = S + (SPLIT ? 2 * G::AF : G::AF);
        #pragma unroll
        for (int s = 0; s < CH / 8; s++) {
            const int kc = s * 8 + (lane & 3);
            uint32_t af[4][4], bf[8][2];
            #pragma unroll
            for (int mt = 0; mt < 4; mt++) {
                int r = wm * 64 + mt * 16 + (lane >> 2);
                af[mt][0] = SA[r * G::RS + kc];
                af[mt][1] = SA[(r + 8) * G::RS + kc];
                af[mt][2] = SA[r * G::RS + kc + 4];
                af[mt][3] = SA[(r + 8) * G::RS + kc + 4];
            }
            #pragma unroll
            for (int nt = 0; nt < 8; nt++) {
                int n = wn * 64 + nt * 8 + (lane >> 2);
                bf[nt][0] = SB[n * G::RS + kc];
                bf[nt][1] = SB[n * G::RS + kc + 4];
            }
            if (!SPLIT) {
                #pragma unroll
                for (int mt = 0; mt < 4; mt++)
                    #pragma unroll
                    for (int nt = 0; nt < 8; nt++)
                        mma8(acc[mt][nt], af[mt], bf[nt]);
            } else {
                const uint32_t* SAl = SA + G::AF;
                const uint32_t* SBl = SB + G::BFl;
                uint32_t al[4][4], bl[8][2];
                #pragma unroll
                for (int mt = 0; mt < 4; mt++) {
                    int r = wm * 64 + mt * 16 + (lane >> 2);
                    al[mt][0] = SAl[r * G::RS + kc];
                    al[mt][1] = SAl[(r + 8) * G::RS + kc];
                    al[mt][2] = SAl[r * G::RS + kc + 4];
                    al[mt][3] = SAl[(r + 8) * G::RS + kc + 4];
                }
                #pragma unroll
                for (int nt = 0; nt < 8; nt++) {
                    int n = wn * 64 + nt * 8 + (lane >> 2);
                    bl[nt][0] = SBl[n * G::RS + kc];
                    bl[nt][1] = SBl[n * G::RS + kc + 4];
                }
                #pragma unroll
                for (int mt = 0; mt < 4; mt++)
                    #pragma unroll
                    for (int nt = 0; nt < 8; nt++) {
                        mma8(acc[mt][nt], af[mt], bf[nt]);
                        mma8(acc[mt][nt], af[mt], bl[nt]);
                        mma8(acc[mt][nt], al[mt], bf[nt]);
                    }
            }
        }
    };

    // ---- pipelined driver --------------------------------------------------
    LD(0); ST(0); __syncthreads();
    for (int c = 0; c < KC; c++) {
        if (c + 1 < KC) LD(c + 1);
        CMP(c & 1);
        __syncthreads();
        if (c + 1 < KC) { ST((c + 1) & 1); __syncthreads(); }
    }
}

// ===========================================================================
// transpose img [b][c][n] -> g_imgT [b][n][c]
// ===========================================================================
__global__ __launch_bounds__(256) void transpose_img_kernel(const float* __restrict__ img)
{
    __shared__ float sm[32][33];
    int tx = threadIdx.x & 31, ty = threadIdx.x >> 5;
    int n0 = blockIdx.x * 32, c0 = blockIdx.y * 32, b = blockIdx.z;
    #pragma unroll
    for (int j = 0; j < 4; j++) {
        int c = ty + j * 8;
        sm[c][tx] = img[((size_t)b * CC + c0 + c) * NN + n0 + tx];
    }
    __syncthreads();
    #pragma unroll
    for (int j = 0; j < 4; j++) {
        int n = ty + j * 8;
        g_imgT[((size_t)b * NN + n0 + n) * CC + c0 + tx] = sm[tx][n];
    }
}

// ===========================================================================
// pc [b][d16][h][w][c16] -> g_pcT [b][h*64+w][c*16+d]
// ===========================================================================
__global__ __launch_bounds__(256) void transpose_pc_kernel(const float* __restrict__ pc)
{
    extern __shared__ float smp[];   // [16][1025]
    int h = blockIdx.x, b = blockIdx.y;
    int t = threadIdx.x;
    for (int i = t; i < 16384; i += 256) {
        int d = i >> 10, r = i & 1023;
        smp[d * 1025 + r] = pc[((size_t)(b * 16 + d) * 64 + h) * 1024 + r];
    }
    __syncthreads();
    for (int j = t; j < 16384; j += 256) {
        int w = j >> 8, col = j & 255;
        int c = col >> 4, d = col & 15;
        g_pcT[((size_t)b * NN + h * 64 + w) * CC + col] = smp[d * 1025 + w * 16 + c];
    }
}

// ===========================================================================
// proj: z = b*4 + job; plain tf32-RN
//   0: Q = imgT*Wq^T+bq -> g_Q | 1: K = pcT*Wk^T+bk -> g_K
//   2: Vimg -> g_Vt[0..256) transposed | 3: Vpc -> g_Vt[256..512) transposed
// ===========================================================================
__global__ void __launch_bounds__(128, 2) proj_kernel(
    const float* __restrict__ wq,  const float* __restrict__ bq,
    const float* __restrict__ wk,  const float* __restrict__ bk,
    const float* __restrict__ wvi, const float* __restrict__ bvi,
    const float* __restrict__ wvp, const float* __restrict__ bvp)
{
    extern __shared__ float sm[];
    int job = blockIdx.z & 3, b = blockIdx.z >> 2;
    int m0 = blockIdx.x * 128, n0 = blockIdx.y * 128;

    const float* A; const float* W; const float* bias;
    switch (job) {
        case 0:  A = g_imgT + (size_t)b * NN * CC; W = wq;  bias = bq;  break;
        case 1:  A = g_pcT  + (size_t)b * NN * CC; W = wk;  bias = bk;  break;
        case 2:  A = g_imgT + (size_t)b * NN * CC; W = wvi; bias = bvi; break;
        default: A = g_pcT  + (size_t)b * NN * CC; W = wvp; bias = bvp; break;
    }

    float acc[4][8][4] = {};
    gemm_run<128, 32, false>(A, CC, m0, W, CC, n0, CC, sm, acc);

    int t = threadIdx.x, lane = t & 31, wid = t >> 5;
    int wm = wid & 1, wn = wid >> 1;

    if (job < 2) {
        float* C = (job == 0 ? g_Q : g_K) + (size_t)b * NN * CC;
        #pragma unroll
        for (int mt = 0; mt < 4; mt++)
            #pragma unroll
            for (int nt = 0; nt < 8; nt++)
                #pragma unroll
                for (int qq = 0; qq < 2; qq++) {
                    int m = m0 + wm * 64 + mt * 16 + (lane >> 2) + 8 * qq;
                    int n = n0 + wn * 64 + nt * 8 + 2 * (lane & 3);
                    float2 bv = *(const float2*)(bias + n);
                    float2 o = { acc[mt][nt][2 * qq + 0] + bv.x,
                                 acc[mt][nt][2 * qq + 1] + bv.y };
                    *(float2*)(C + (size_t)m * CC + n) = o;
                }
    } else {
        // transposed write via smem patch (PS = 132)
        int voff = (job == 2) ? 0 : 256;
        float* patch = sm;
        #pragma unroll
        for (int mt = 0; mt < 4; mt++)
            #pragma unroll
            for (int nt = 0; nt < 8; nt++)
                #pragma unroll
                for (int q = 0; q < 4; q++) {
                    int m = wm * 64 + mt * 16 + (lane >> 2) + 8 * (q >> 1);
                    int n = wn * 64 + nt * 8 + 2 * (lane & 3) + (q & 1);
                    patch[n * 132 + m] = acc[mt][nt][q] + bias[n0 + n];
                }
        __syncthreads();
        int u = t & 7, cr = t >> 3;          // 16 c-rows per pass
        #pragma unroll
        for (int cc = 0; cc < 8; cc++) {
            int c = cc * 16 + cr;
            float* dst = g_Vt + ((size_t)b * CV + voff + n0 + c) * NN + m0;
            #pragma unroll
            for (int k4 = 0; k4 < 4; k4++) {
                int m = k4 * 32 + u * 4;
                *(float4*)(dst + m) = *(float4*)(patch + c * 132 + m);
            }
        }
    }
}

// ===========================================================================
// qk: S[m][n] = Q[m].K[n]  (SPLIT tf32, ~fp32 quality)
// ===========================================================================
__global__ void __launch_bounds__(128, 2) qk_kernel()
{
    extern __shared__ float sm[];
    int b = blockIdx.z;
    int m0 = blockIdx.y * 128, n0 = blockIdx.x * 128;

    float acc[4][8][4] = {};
    gemm_run<128, 16, true>(g_Q + (size_t)b * NN * CC, CC, m0,
                            g_K + (size_t)b * NN * CC, CC, n0, CC, sm, acc);

    int t = threadIdx.x, lane = t & 31, wid = t >> 5;
    int wm = wid & 1, wn = wid >> 1;
    float* Sg = g_S + (size_t)b * NN * NN;
    #pragma unroll
    for (int mt = 0; mt < 4; mt++)
        #pragma unroll
        for (int nt = 0; nt < 8; nt++)
            #pragma unroll
            for (int qq = 0; qq < 2; qq++) {
                int m = m0 + wm * 64 + mt * 16 + (lane >> 2) + 8 * qq;
                int n = n0 + wn * 64 + nt * 8 + 2 * (lane & 3);
                float2 o = { acc[mt][nt][2 * qq + 0], acc[mt][nt][2 * qq + 1] };
                *(float2*)(Sg + (size_t)m * NN + n) = o;
            }
}

// ===========================================================================
// softmax rows of g_S (in place)
// ===========================================================================
__global__ __launch_bounds__(256) void softmax_kernel()
{
    size_t row = blockIdx.x;
    float* p = g_S + row * NN;
    int t = threadIdx.x;

    float4 v[4];
    #pragma unroll
    for (int i = 0; i < 4; i++) v[i] = ((const float4*)p)[(size_t)i * 256 + t];

    float mx = -1e30f;
    #pragma unroll
    for (int i = 0; i < 4; i++)
        mx = fmaxf(mx, fmaxf(fmaxf(v[i].x, v[i].y), fmaxf(v[i].z, v[i].w)));
    __shared__ float red[8];
    #pragma unroll
    for (int o = 16; o; o >>= 1) mx = fmaxf(mx, __shfl_xor_sync(0xFFFFFFFFu, mx, o));
    if ((t & 31) == 0) red[t >> 5] = mx;
    __syncthreads();
    if (t < 8) {
        float m = red[t];
        #pragma unroll
        for (int o = 4; o; o >>= 1) m = fmaxf(m, __shfl_xor_sync(0xFFu, m, o));
        if (t == 0) red[0] = m;
    }
    __syncthreads();
    mx = red[0];
    __syncthreads();

    float s = 0.f;
    #pragma unroll
    for (int i = 0; i < 4; i++) {
        v[i].x = __expf(v[i].x - mx); s += v[i].x;
        v[i].y = __expf(v[i].y - mx); s += v[i].y;
        v[i].z = __expf(v[i].z - mx); s += v[i].z;
        v[i].w = __expf(v[i].w - mx); s += v[i].w;
    }
    #pragma unroll
    for (int o = 16; o; o >>= 1) s += __shfl_xor_sync(0xFFFFFFFFu, s, o);
    if ((t & 31) == 0) red[t >> 5] = s;
    __syncthreads();
    if (t < 8) {
        float m = red[t];
        #pragma unroll
        for (int o = 4; o; o >>= 1) m += __shfl_xor_sync(0xFFu, m, o);
        if (t == 0) red[0] = m;
    }
    __syncthreads();
    float inv = 1.0f / red[0];

    #pragma unroll
    for (int i = 0; i < 4; i++) {
        v[i].x *= inv; v[i].y *= inv; v[i].z *= inv; v[i].w *= inv;
        ((float4*)p)[(size_t)i * 256 + t] = v[i];
    }
}

// ===========================================================================
// out: O[m][c] = sum_n P[m][n] * Vt[c][n]; BN=256, K=4096, plain tf32
// grid (32 m-tiles, 2 c-halves, B). Transposed epilogue -> d_out [c][m].
// ===========================================================================
__global__ void __launch_bounds__(256, 1) out_kernel(float* __restrict__ out)
{
    extern __shared__ float sm[];
    int b = blockIdx.z;
    int m0 = blockIdx.x * 128;
    int half = blockIdx.y;
    const float* P = g_S  + (size_t)b * NN * NN;
    const float* V = g_Vt + ((size_t)b * CV + half * 256) * NN;

    float acc[4][8][4] = {};
    gemm_run<256, 32, false>(P, NN, m0, V, NN, 0, NN, sm, acc);

    int t = threadIdx.x, lane = t & 31, wid = t >> 5;
    int wm = wid & 1, wn = wid >> 1;         // wn 0..3
    float* patch = sm;
    const size_t pcOff = (size_t)BB * 256 * NN;

    #pragma unroll
    for (int nh = 0; nh < 2; nh++) {
        __syncthreads();
        if ((wn >> 1) == nh) {
            int wnl = wn & 1;
            #pragma unroll
            for (int mt = 0; mt < 4; mt++)
                #pragma unroll
                for (int nt = 0; nt < 8; nt++)
                    #pragma unroll
                    for (int q = 0; q < 4; q++) {
                        int m = wm * 64 + mt * 16 + (lane >> 2) + 8 * (q >> 1);
                        int n = wnl * 64 + nt * 8 + 2 * (lane & 3) + (q & 1);
                        patch[n * 132 + m] = acc[mt][nt][q];
                    }
        }
        __syncthreads();
        int u = t & 7, cr = t >> 3;          // 32 c-rows per pass
        #pragma unroll
        for (int cc = 0; cc < 4; cc++) {
            int c = cc * 32 + cr;
            int cg = half * 256 + nh * 128 + c;      // 0..511
            float* dst = (cg < 256)
                ? out + (size_t)(b * 256 + cg) * NN + m0
                : out + pcOff + (size_t)(b * 256 + cg - 256) * NN + m0;
            #pragma unroll
            for (int k4 = 0; k4 < 4; k4++) {
                int m = k4 * 32 + u * 4;
                *(float4*)(dst + m) = *(float4*)(patch + c * 132 + m);
            }
        }
    }
}

// ===========================================================================
extern "C" void kernel_launch(void* const* d_in, const int* in_sizes, int n_in,
                              void* d_out, int out_size)
{
    const float* img  = (const float*)d_in[0];
    const float* pc   = (const float*)d_in[1];
    const float* w_q  = (const float*)d_in[2];
    const float* b_q  = (const float*)d_in[3];
    const float* w_k  = (const float*)d_in[4];
    const float* b_k  = (const float*)d_in[5];
    const float* w_vi = (const float*)d_in[6];
    const float* b_vi = (const float*)d_in[7];
    const float* w_vp = (const float*)d_in[8];
    const float* b_vp = (const float*)d_in[9];
    float* out = (float*)d_out;

    constexpr int SM_PROJ = GemmCfg<128, 32, false>::SMEM_BYTES;  // 73728
    constexpr int SM_QK   = GemmCfg<128, 16, true >::SMEM_BYTES;  // 81920
    constexpr int SM_OUT  = GemmCfg<256, 32, false>::SMEM_BYTES;  // 110592

    static int configured = 0;
    if (!configured) {
        cudaFuncSetAttribute(transpose_pc_kernel,
                             cudaFuncAttributeMaxDynamicSharedMemorySize, 16 * 1025 * 4);
        cudaFuncSetAttribute(proj_kernel,
                             cudaFuncAttributeMaxDynamicSharedMemorySize, SM_PROJ);
        cudaFuncSetAttribute(qk_kernel,
                             cudaFuncAttributeMaxDynamicSharedMemorySize, SM_QK);
        cudaFuncSetAttribute(out_kernel,
                             cudaFuncAttributeMaxDynamicSharedMemorySize, SM_OUT);
        configured = 1;
    }

    transpose_img_kernel<<<dim3(NN / 32, CC / 32, BB), 256>>>(img);
    transpose_pc_kernel<<<dim3(64, BB), 256, 16 * 1025 * 4>>>(pc);
    proj_kernel<<<dim3(NN / 128, CC / 128, BB * 4), 128, SM_PROJ>>>(
        w_q, b_q, w_k, b_k, w_vi, b_vi, w_vp, b_vp);
    qk_kernel<<<dim3(NN / 128, NN / 128, BB), 128, SM_QK>>>();
    softmax_kernel<<<BB * NN, 256>>>();
    out_kernel<<<dim3(NN / 128, 2, BB), 256, SM_OUT>>>(out);
}

// round 5
// speedup vs baseline: 2.3791x; 1.0579x over previous
#include <cuda_runtime.h>
#include <cstdint>

#define BB 2
#define NN 4096           // H*W
#define CC 256            // QK_DIM
#define CV 512            // concat V width

// ---- scratch (device globals; allocation-free) ----
__device__ float g_imgT[(size_t)BB * NN * CC];   // [b][n][256]
__device__ float g_pcT [(size_t)BB * NN * CC];   // [b][n][256]  col = c*16+d
__device__ float g_Q   [(size_t)BB * NN * CC];   // [b][n][256]
__device__ float g_K   [(size_t)BB * NN * CC];   // [b][n][256]
__device__ float g_Vt  [(size_t)BB * CV * NN];   // [b][c(512)][n]
__device__ float g_S   [(size_t)BB * NN * NN];   // [b][m][n]

// ===========================================================================
// helpers
// ===========================================================================
__device__ __forceinline__ uint32_t prmt_hi(uint32_t a, uint32_t b) {
    // pack top-16 bits of a (lo half) and b (hi half): bf16x2 {lo=a_hi16, hi=b_hi16}
    uint32_t r; asm("prmt.b32 %0, %1, %2, 0x7632;" : "=r"(r) : "r"(a), "r"(b)); return r;
}
__device__ __forceinline__ uint32_t cvt_bf16x2(float hi, float lo) {
    uint32_t r; asm("cvt.rn.bf16x2.f32 %0, %1, %2;" : "=r"(r) : "f"(hi), "f"(lo)); return r;
}
__device__ __forceinline__ float truncb(float x) {
    return __uint_as_float(__float_as_uint(x) & 0xFFFF0000u);
}
__device__ __forceinline__ void mma16(float* d, const uint32_t* a, const uint32_t* b) {
    asm("mma.sync.aligned.m16n8k16.row.col.f32.bf16.bf16.f32 "
        "{%0,%1,%2,%3}, {%4,%5,%6,%7}, {%8,%9}, {%0,%1,%2,%3};"
        : "+f"(d[0]), "+f"(d[1]), "+f"(d[2]), "+f"(d[3])
        : "r"(a[0]), "r"(a[1]), "r"(a[2]), "r"(a[3]), "r"(b[0]), "r"(b[1]));
}

// ===========================================================================
// split-bf16 GEMM core (3-MMA hi/lo split, ~1e-5 relative error)
//   C[128][256] += A[aRow0..+128][K] * B[bRow0..+256][K]^T  (both K-major)
//   256 threads, warp grid 2(m)x4(n), warp tile 64x64, K chunk 32.
//   smem: bf16 tiles, k-pairs packed in 32-bit words, row stride 20 words
//   (16 data + 4 pad -> conflict-free LDS.32 fragment loads).
// ===========================================================================
#define RS32  20
#define W_AH  0
#define W_AL  (128 * RS32)            // 2560
#define W_BH  (2 * 128 * RS32)       // 5120
#define W_BL  (W_BH + 256 * RS32)    // 10240
#define STW   (W_BL + 256 * RS32)    // 15360 words / stage
#define SMEM_GEMM (2 * STW * 4)      // 122880 bytes

__device__ __forceinline__ void gemm_bf16s(
    const float* __restrict__ A, int lda, int aRow0,
    const float* __restrict__ B, int ldb, int bRow0,
    int K, uint32_t* sw, float (&acc)[4][8][4])
{
    const int t    = threadIdx.x;
    const int lane = t & 31;
    const int wid  = t >> 5;
    const int wm   = wid & 1;
    const int wn   = wid >> 1;
    const int KC   = K >> 5;

    float4 ra[4], rb[8];

    auto LD = [&](int c) {
        const int k0 = c << 5;
        #pragma unroll
        for (int i = 0; i < 4; i++) {
            int f = t + (i << 8), m = f >> 3, j = f & 7;
            ra[i] = *(const float4*)(A + (size_t)(aRow0 + m) * lda + k0 + 4 * j);
        }
        #pragma unroll
        for (int i = 0; i < 8; i++) {
            int f = t + (i << 8), m = f >> 3, j = f & 7;
            rb[i] = *(const float4*)(B + (size_t)(bRow0 + m) * ldb + k0 + 4 * j);
        }
    };
    auto ST = [&](int buf) {
        uint32_t* S = sw + buf * STW;
        #pragma unroll
        for (int i = 0; i < 4; i++) {
            int f = t + (i << 8), m = f >> 3, j = f & 7;
            float4 v = ra[i];
            uint2 h, l;
            h.x = prmt_hi(__float_as_uint(v.x), __float_as_uint(v.y));
            h.y = prmt_hi(__float_as_uint(v.z), __float_as_uint(v.w));
            l.x = cvt_bf16x2(v.y - truncb(v.y), v.x - truncb(v.x));
            l.y = cvt_bf16x2(v.w - truncb(v.w), v.z - truncb(v.z));
            int w = m * RS32 + 2 * j;
            *(uint2*)(S + W_AH + w) = h;
            *(uint2*)(S + W_AL + w) = l;
        }
        #pragma unroll
        for (int i = 0; i < 8; i++) {
            int f = t + (i << 8), m = f >> 3, j = f & 7;
            float4 v = rb[i];
            uint2 h, l;
            h.x = prmt_hi(__float_as_uint(v.x), __float_as_uint(v.y));
            h.y = prmt_hi(__float_as_uint(v.z), __float_as_uint(v.w));
            l.x = cvt_bf16x2(v.y - truncb(v.y), v.x - truncb(v.x));
            l.y = cvt_bf16x2(v.w - truncb(v.w), v.z - truncb(v.z));
            int w = m * RS32 + 2 * j;
            *(uint2*)(S + W_BH + w) = h;
            *(uint2*)(S + W_BL + w) = l;
        }
    };
    auto CMP = [&](int buf) {
        const uint32_t* S = sw + buf * STW;
        #pragma unroll
        for (int s = 0; s < 2; s++) {
            const int kw = (s << 3) + (lane & 3);
            uint32_t ah[4][4], al[4][4];
            #pragma unroll
            for (int mt = 0; mt < 4; mt++) {
                int r = wm * 64 + mt * 16 + (lane >> 2);
                ah[mt][0] = S[W_AH + r * RS32 + kw];
                ah[mt][1] = S[W_AH + (r + 8) * RS32 + kw];
                ah[mt][2] = S[W_AH + r * RS32 + kw + 4];
                ah[mt][3] = S[W_AH + (r + 8) * RS32 + kw + 4];
                al[mt][0] = S[W_AL + r * RS32 + kw];
                al[mt][1] = S[W_AL + (r + 8) * RS32 + kw];
                al[mt][2] = S[W_AL + r * RS32 + kw + 4];
                al[mt][3] = S[W_AL + (r + 8) * RS32 + kw + 4];
            }
            #pragma unroll
            for (int nt = 0; nt < 8; nt++) {
                int n = wn * 64 + nt * 8 + (lane >> 2);
                uint32_t bh[2], bl[2];
                bh[0] = S[W_BH + n * RS32 + kw];
                bh[1] = S[W_BH + n * RS32 + kw + 4];
                bl[0] = S[W_BL + n * RS32 + kw];
                bl[1] = S[W_BL + n * RS32 + kw + 4];
                #pragma unroll
                for (int mt = 0; mt < 4; mt++) {
                    mma16(acc[mt][nt], ah[mt], bh);
                    mma16(acc[mt][nt], ah[mt], bl);
                    mma16(acc[mt][nt], al[mt], bh);
                }
            }
        }
    };

    LD(0); ST(0); __syncthreads();
    for (int c = 0; c < KC; c++) {
        if (c + 1 < KC) LD(c + 1);
        CMP(c & 1);
        __syncthreads();
        if (c + 1 < KC) { ST((c + 1) & 1); __syncthreads(); }
    }
}

// ===========================================================================
// transpose img [b][c][n] -> g_imgT [b][n][c]
// ===========================================================================
__global__ __launch_bounds__(256) void transpose_img_kernel(const float* __restrict__ img)
{
    __shared__ float sm[32][33];
    int tx = threadIdx.x & 31, ty = threadIdx.x >> 5;
    int n0 = blockIdx.x * 32, c0 = blockIdx.y * 32, b = blockIdx.z;
    #pragma unroll
    for (int j = 0; j < 4; j++) {
        int c = ty + j * 8;
        sm[c][tx] = img[((size_t)b * CC + c0 + c) * NN + n0 + tx];
    }
    __syncthreads();
    #pragma unroll
    for (int j = 0; j < 4; j++) {
        int n = ty + j * 8;
        g_imgT[((size_t)b * NN + n0 + n) * CC + c0 + tx] = sm[tx][n];
    }
}

// ===========================================================================
// pc [b][d16][h][w][c16] -> g_pcT [b][h*64+w][c*16+d]
// ===========================================================================
__global__ __launch_bounds__(256) void transpose_pc_kernel(const float* __restrict__ pc)
{
    extern __shared__ float smp[];   // [16][1025]
    int h = blockIdx.x, b = blockIdx.y;
    int t = threadIdx.x;
    for (int i = t; i < 16384; i += 256) {
        int d = i >> 10, r = i & 1023;
        smp[d * 1025 + r] = pc[((size_t)(b * 16 + d) * 64 + h) * 1024 + r];
    }
    __syncthreads();
    for (int j = t; j < 16384; j += 256) {
        int w = j >> 8, col = j & 255;
        int c = col >> 4, d = col & 15;
        g_pcT[((size_t)b * NN + h * 64 + w) * CC + col] = smp[d * 1025 + w * 16 + c];
    }
}

// ===========================================================================
// proj: z = b*4 + job; split bf16; block tile 128x256 (full N)
//   0: Q = imgT*Wq^T+bq -> g_Q | 1: K = pcT*Wk^T+bk -> g_K
//   2: Vimg -> g_Vt[0..256) transposed | 3: Vpc -> g_Vt[256..512) transposed
// ===========================================================================
__global__ void __launch_bounds__(256, 1) proj_kernel(
    const float* __restrict__ wq,  const float* __restrict__ bq,
    const float* __restrict__ wk,  const float* __restrict__ bk,
    const float* __restrict__ wvi, const float* __restrict__ bvi,
    const float* __restrict__ wvp, const float* __restrict__ bvp)
{
    extern __shared__ uint32_t sw[];
    int job = blockIdx.z & 3, b = blockIdx.z >> 2;
    int m0 = blockIdx.x * 128;

    const float* A; const float* W; const float* bias;
    switch (job) {
        case 0:  A = g_imgT + (size_t)b * NN * CC; W = wq;  bias = bq;  break;
        case 1:  A = g_pcT  + (size_t)b * NN * CC; W = wk;  bias = bk;  break;
        case 2:  A = g_imgT + (size_t)b * NN * CC; W = wvi; bias = bvi; break;
        default: A = g_pcT  + (size_t)b * NN * CC; W = wvp; bias = bvp; break;
    }

    float acc[4][8][4] = {};
    gemm_bf16s(A, CC, m0, W, CC, 0, CC, sw, acc);

    int t = threadIdx.x, lane = t & 31, wid = t >> 5;
    int wm = wid & 1, wn = wid >> 1;

    if (job < 2) {
        float* C = (job == 0 ? g_Q : g_K) + (size_t)b * NN * CC;
        #pragma unroll
        for (int mt = 0; mt < 4; mt++)
            #pragma unroll
            for (int nt = 0; nt < 8; nt++)
                #pragma unroll
                for (int qq = 0; qq < 2; qq++) {
                    int m = m0 + wm * 64 + mt * 16 + (lane >> 2) + 8 * qq;
                    int n = wn * 64 + nt * 8 + 2 * (lane & 3);
                    float2 bv = *(const float2*)(bias + n);
                    float2 o = { acc[mt][nt][2 * qq + 0] + bv.x,
                                 acc[mt][nt][2 * qq + 1] + bv.y };
                    *(float2*)(C + (size_t)m * CC + n) = o;
                }
    } else {
        int voff = (job == 2) ? 0 : 256;
        float* patch = (float*)sw;
        #pragma unroll
        for (int nh = 0; nh < 2; nh++) {
            __syncthreads();
            if ((wn >> 1) == nh) {
                int wnl = wn & 1;
                #pragma unroll
                for (int mt = 0; mt < 4; mt++)
                    #pragma unroll
                    for (int nt = 0; nt < 8; nt++)
                        #pragma unroll
                        for (int q = 0; q < 4; q++) {
                            int m = wm * 64 + mt * 16 + (lane >> 2) + 8 * (q >> 1);
                            int n = wnl * 64 + nt * 8 + 2 * (lane & 3) + (q & 1);
                            patch[n * 132 + m] = acc[mt][nt][q] + bias[nh * 128 + n];
                        }
            }
            __syncthreads();
            int u = t & 7, cr = t >> 3;          // 32 c-rows per pass
            #pragma unroll
            for (int cc = 0; cc < 4; cc++) {
                int c = cc * 32 + cr;
                float* dst = g_Vt + ((size_t)b * CV + voff + nh * 128 + c) * NN + m0;
                #pragma unroll
                for (int k4 = 0; k4 < 4; k4++) {
                    int m = k4 * 32 + u * 4;
                    *(float4*)(dst + m) = *(float4*)(patch + c * 132 + m);
                }
            }
        }
    }
}

// ===========================================================================
// qk: S[m][n] = Q[m].K[n]  (split bf16); block tile 128x256
// ===========================================================================
__global__ void __launch_bounds__(256, 1) qk_kernel()
{
    extern __shared__ uint32_t sw[];
    int b = blockIdx.z;
    int m0 = blockIdx.y * 128, n0 = blockIdx.x * 256;

    float acc[4][8][4] = {};
    gemm_bf16s(g_Q + (size_t)b * NN * CC, CC, m0,
               g_K + (size_t)b * NN * CC, CC, n0, CC, sw, acc);

    int t = threadIdx.x, lane = t & 31, wid = t >> 5;
    int wm = wid & 1, wn = wid >> 1;
    float* Sg = g_S + (size_t)b * NN * NN;
    #pragma unroll
    for (int mt = 0; mt < 4; mt++)
        #pragma unroll
        for (int nt = 0; nt < 8; nt++)
            #pragma unroll
            for (int qq = 0; qq < 2; qq++) {
                int m = m0 + wm * 64 + mt * 16 + (lane >> 2) + 8 * qq;
                int n = n0 + wn * 64 + nt * 8 + 2 * (lane & 3);
                float2 o = { acc[mt][nt][2 * qq + 0], acc[mt][nt][2 * qq + 1] };
                *(float2*)(Sg + (size_t)m * NN + n) = o;
            }
}

// ===========================================================================
// softmax rows of g_S (in place)
// ===========================================================================
__global__ __launch_bounds__(256) void softmax_kernel()
{
    size_t row = blockIdx.x;
    float* p = g_S + row * NN;
    int t = threadIdx.x;

    float4 v[4];
    #pragma unroll
    for (int i = 0; i < 4; i++) v[i] = ((const float4*)p)[(size_t)i * 256 + t];

    float mx = -1e30f;
    #pragma unroll
    for (int i = 0; i < 4; i++)
        mx = fmaxf(mx, fmaxf(fmaxf(v[i].x, v[i].y), fmaxf(v[i].z, v[i].w)));
    __shared__ float red[8];
    #pragma unroll
    for (int o = 16; o; o >>= 1) mx = fmaxf(mx, __shfl_xor_sync(0xFFFFFFFFu, mx, o));
    if ((t & 31) == 0) red[t >> 5] = mx;
    __syncthreads();
    if (t < 8) {
        float m = red[t];
        #pragma unroll
        for (int o = 4; o; o >>= 1) m = fmaxf(m, __shfl_xor_sync(0xFFu, m, o));
        if (t == 0) red[0] = m;
    }
    __syncthreads();
    mx = red[0];
    __syncthreads();

    float s = 0.f;
    #pragma unroll
    for (int i = 0; i < 4; i++) {
        v[i].x = __expf(v[i].x - mx); s += v[i].x;
        v[i].y = __expf(v[i].y - mx); s += v[i].y;
        v[i].z = __expf(v[i].z - mx); s += v[i].z;
        v[i].w = __expf(v[i].w - mx); s += v[i].w;
    }
    #pragma unroll
    for (int o = 16; o; o >>= 1) s += __shfl_xor_sync(0xFFFFFFFFu, s, o);
    if ((t & 31) == 0) red[t >> 5] = s;
    __syncthreads();
    if (t < 8) {
        float m = red[t];
        #pragma unroll
        for (int o = 4; o; o >>= 1) m += __shfl_xor_sync(0xFFu, m, o);
        if (t == 0) red[0] = m;
    }
    __syncthreads();
    float inv = 1.0f / red[0];

    #pragma unroll
    for (int i = 0; i < 4; i++) {
        v[i].x *= inv; v[i].y *= inv; v[i].z *= inv; v[i].w *= inv;
        ((float4*)p)[(size_t)i * 256 + t] = v[i];
    }
}

// ===========================================================================
// out: O[m][c] = sum_n P[m][n] * Vt[c][n]; split bf16; K = 4096
// grid (32 m-tiles, 2 c-halves, B). Transposed epilogue -> d_out [c][m].
// ===========================================================================
__global__ void __launch_bounds__(256, 1) out_kernel(float* __restrict__ out)
{
    extern __shared__ uint32_t sw[];
    int b = blockIdx.z;
    int m0 = blockIdx.x * 128;
    int half = blockIdx.y;
    const float* P = g_S  + (size_t)b * NN * NN;
    const float* V = g_Vt + ((size_t)b * CV + half * 256) * NN;

    float acc[4][8][4] = {};
    gemm_bf16s(P, NN, m0, V, NN, 0, NN, sw, acc);

    int t = threadIdx.x, lane = t & 31, wid = t >> 5;
    int wm = wid & 1, wn = wid >> 1;         // wn 0..3
    float* patch = (float*)sw;
    const size_t pcOff = (size_t)BB * 256 * NN;

    #pragma unroll
    for (int nh = 0; nh < 2; nh++) {
        __syncthreads();
        if ((wn >> 1) == nh) {
            int wnl = wn & 1;
            #pragma unroll
            for (int mt = 0; mt < 4; mt++)
                #pragma unroll
                for (int nt = 0; nt < 8; nt++)
                    #pragma unroll
                    for (int q = 0; q < 4; q++) {
                        int m = wm * 64 + mt * 16 + (lane >> 2) + 8 * (q >> 1);
                        int n = wnl * 64 + nt * 8 + 2 * (lane & 3) + (q & 1);
                        patch[n * 132 + m] = acc[mt][nt][q];
                    }
        }
        __syncthreads();
        int u = t & 7, cr = t >> 3;          // 32 c-rows per pass
        #pragma unroll
        for (int cc = 0; cc < 4; cc++) {
            int c = cc * 32 + cr;
            int cg = half * 256 + nh * 128 + c;      // 0..511
            float* dst = (cg < 256)
                ? out + (size_t)(b * 256 + cg) * NN + m0
                : out + pcOff + (size_t)(b * 256 + cg - 256) * NN + m0;
            #pragma unroll
            for (int k4 = 0; k4 < 4; k4++) {
                int m = k4 * 32 + u * 4;
                *(float4*)(dst + m) = *(float4*)(patch + c * 132 + m);
            }
        }
    }
}

// ===========================================================================
extern "C" void kernel_launch(void* const* d_in, const int* in_sizes, int n_in,
                              void* d_out, int out_size)
{
    const float* img  = (const float*)d_in[0];
    const float* pc   = (const float*)d_in[1];
    const float* w_q  = (const float*)d_in[2];
    const float* b_q  = (const float*)d_in[3];
    const float* w_k  = (const float*)d_in[4];
    const float* b_k  = (const float*)d_in[5];
    const float* w_vi = (const float*)d_in[6];
    const float* b_vi = (const float*)d_in[7];
    const float* w_vp = (const float*)d_in[8];
    const float* b_vp = (const float*)d_in[9];
    float* out = (float*)d_out;

    static int configured = 0;
    if (!configured) {
        cudaFuncSetAttribute(transpose_pc_kernel,
                             cudaFuncAttributeMaxDynamicSharedMemorySize, 16 * 1025 * 4);
        cudaFuncSetAttribute(proj_kernel,
                             cudaFuncAttributeMaxDynamicSharedMemorySize, SMEM_GEMM);
        cudaFuncSetAttribute(qk_kernel,
                             cudaFuncAttributeMaxDynamicSharedMemorySize, SMEM_GEMM);
        cudaFuncSetAttribute(out_kernel,
                             cudaFuncAttributeMaxDynamicSharedMemorySize, SMEM_GEMM);
        configured = 1;
    }

    transpose_img_kernel<<<dim3(NN / 32, CC / 32, BB), 256>>>(img);
    transpose_pc_kernel<<<dim3(64, BB), 256, 16 * 1025 * 4>>>(pc);
    proj_kernel<<<dim3(NN / 128, 1, BB * 4), 256, SMEM_GEMM>>>(
        w_q, b_q, w_k, b_k, w_vi, b_vi, w_vp, b_vp);
    qk_kernel<<<dim3(NN / 256, NN / 128, BB), 256, SMEM_GEMM>>>();
    softmax_kernel<<<BB * NN, 256>>>();
    out_kernel<<<dim3(NN / 128, 2, BB), 256, SMEM_GEMM>>>(out);
}